// round 16
// baseline (speedup 1.0000x reference)
#include <cuda_runtime.h>
#include <cuda_bf16.h>
#include <math.h>
#include <stdint.h>

#define EMB 128
#define WINDOW 200
#define DK 32
#define NH 8
#define NT 50
#define NB 1024

#define OUT_ELEMS (NB*NT*EMB)          // 6,553,600
#define ATT_ELEMS (NB*NH*NT*WINDOW)    // 81,920,000

// ---------------- scratch (device globals; no runtime allocation) ----------
// packed rows: 64 bf16 = [0:32) hi | [32:64) lo residual
__device__ __nv_bfloat16 g_qp[NB*NH*NT*64];       // q-hat packed
__device__ __nv_bfloat16 g_kp[NB*NH*WINDOW*64];   // k-hat packed
__device__ __nv_bfloat16 g_vb[NB*NH*WINDOW*64];   // v packed (no norm)
__device__ float g_oh[NB*NT*NH*DK];               // out heads (b,t,h*32+d)
__device__ float g_rt [256*EMB];                  // R_w transposed: [o][e]
__device__ __nv_bfloat16 g_wbhi[3*256*EMB];       // W hi bf16, [o][k]
__device__ __nv_bfloat16 g_wblo[3*256*EMB];       // W lo residual bf16

// ================= helpers ==================================================
__device__ __forceinline__ uint32_t smem_u32(const void* p) {
    uint32_t a;
    asm("{ .reg .u64 t; cvta.to.shared.u64 t, %1; cvt.u32.u64 %0, t; }"
        : "=r"(a) : "l"(p));
    return a;
}

__device__ __forceinline__ float2 ffma2(float2 a, float2 b, float2 c) {
    unsigned long long au, bu, cu, du;
    asm("mov.b64 %0, {%1, %2};" : "=l"(au) : "f"(a.x), "f"(a.y));
    asm("mov.b64 %0, {%1, %2};" : "=l"(bu) : "f"(b.x), "f"(b.y));
    asm("mov.b64 %0, {%1, %2};" : "=l"(cu) : "f"(c.x), "f"(c.y));
    asm("fma.rn.f32x2 %0, %1, %2, %3;" : "=l"(du) : "l"(au), "l"(bu), "l"(cu));
    float2 r;
    asm("mov.b64 {%0, %1}, %2;" : "=f"(r.x), "=f"(r.y) : "l"(du));
    return r;
}

#define LDSM_X4(d, addr) \
    asm volatile("ldmatrix.sync.aligned.m8n8.x4.shared.b16 {%0,%1,%2,%3}, [%4];" \
        : "=r"((d)[0]), "=r"((d)[1]), "=r"((d)[2]), "=r"((d)[3]) : "r"(addr))

#define LDSM_X4_T(d, addr) \
    asm volatile("ldmatrix.sync.aligned.m8n8.x4.trans.shared.b16 {%0,%1,%2,%3}, [%4];" \
        : "=r"((d)[0]), "=r"((d)[1]), "=r"((d)[2]), "=r"((d)[3]) : "r"(addr))

#define MMA_BF16(c, a, b) \
    asm volatile("mma.sync.aligned.m16n8k16.row.col.f32.bf16.bf16.f32 " \
        "{%0,%1,%2,%3}, {%4,%5,%6,%7}, {%8,%9}, {%0,%1,%2,%3};" \
        : "+f"((c)[0]), "+f"((c)[1]), "+f"((c)[2]), "+f"((c)[3]) \
        : "r"((a)[0]), "r"((a)[1]), "r"((a)[2]), "r"((a)[3]), \
          "r"((b)[0]), "r"((b)[1]))

__device__ __forceinline__ void pack_hilo(float x0, float x1,
                                          uint32_t& hi, uint32_t& lo) {
    __nv_bfloat162 h = __floats2bfloat162_rn(x0, x1);
    float r0 = x0 - __low2float(h), r1 = x1 - __high2float(h);
    __nv_bfloat162 l = __floats2bfloat162_rn(r0, r1);
    uint32_t hu, lu;
    memcpy(&hu, &h, 4); memcpy(&lu, &l, 4);
    hi = hu; lo = lu;
}

// ---------------- prep: W bf16 hi/lo split + R transpose --------------------
__global__ void prep_w(const float* __restrict__ At, const float* __restrict__ Ac,
                       const float* __restrict__ Bc, const float* __restrict__ R)
{
    int i = blockIdx.x * 256 + threadIdx.x;
    if (i < 32768) {
        const float* srcs[3] = {At, Ac, Bc};
        #pragma unroll
        for (int m = 0; m < 3; m++) {
            float a  = srcs[m][i];
            __nv_bfloat16 h = __float2bfloat16_rn(a);
            float lo = a - __bfloat162float(h);
            g_wbhi[m*32768 + i] = h;
            g_wblo[m*32768 + i] = __float2bfloat16_rn(lo);
        }
        int e = i >> 8, oo = i & 255;
        g_rt[oo*128 + e] = R[i];
    }
}

// ---------------- tensor-core projection (W-resident, 2 blocks/SM) ----------
#define P_AHI 0
#define P_ALO 10240
#define P_WHI 20480
#define P_WLO 55296
#define PROJ_SMEM 90112
#define EPI_PITCH 544

__device__ __forceinline__ void proj_loadA(
    const float* __restrict__ X, int row0, int kk, int tid, float4* xv)
{
    #pragma unroll
    for (int i = 0; i < 4; i++) {
        int idx = tid + i * 256;
        int r = idx >> 3, f4 = idx & 7;
        xv[i] = *(const float4*)(X + (long long)(row0 + r) * EMB + kk*32 + f4*4);
    }
}

__device__ __forceinline__ void proj_storeA(
    char* psm, int tid, const float4* xv)
{
    #pragma unroll
    for (int i = 0; i < 4; i++) {
        int idx = tid + i * 256;
        int r = idx >> 3, f4 = idx & 7;
        float4 x = xv[i];
        uint32_t h0, l0, h1, l1;
        pack_hilo(x.x, x.y, h0, l0);
        pack_hilo(x.z, x.w, h1, l1);
        *(uint2*)(psm + P_AHI + r*80 + f4*8) = make_uint2(h0, h1);
        *(uint2*)(psm + P_ALO + r*80 + f4*8) = make_uint2(l0, l1);
    }
}

template<int RPB, int DST, int NORM>
__global__ __launch_bounds__(256, 2)
void proj_mma(const float* __restrict__ X, const float* __restrict__ bias, int widx)
{
    extern __shared__ char psm[];
    const uint32_t base = smem_u32(psm);

    __nv_bfloat16* __restrict__ Yp = (DST == 0) ? g_qp : (DST == 1) ? g_kp : g_vb;
    const __nv_bfloat16* __restrict__ Whi = g_wbhi + widx * 32768;
    const __nv_bfloat16* __restrict__ Wlo = g_wblo + widx * 32768;

    const int tid    = threadIdx.x;
    const int wid    = tid >> 5;
    const int lane   = tid & 31;
    const int warp_m = wid & 3;
    const int warp_n = wid >> 2;
    const int row0   = blockIdx.x * 128;
    const int nb     = blockIdx.y * 128;

    #pragma unroll
    for (int i = 0; i < 8; i++) {
        int idx = tid + i * 256;
        int r = idx >> 4, g = idx & 15;
        const long long src = (long long)(nb + r) * EMB + g*8;
        *(uint4*)(psm + P_WHI + r*272 + g*16) = *(const uint4*)&Whi[src];
        *(uint4*)(psm + P_WLO + r*272 + g*16) = *(const uint4*)&Wlo[src];
    }

    float4 xv[4];
    proj_loadA(X, row0, 0, tid, xv);
    proj_storeA(psm, tid, xv);
    __syncthreads();

    const int lr = lane & 7;
    const int lq = lane >> 3;
    const uint32_t aoff  = (uint32_t)((warp_m*32 + lr + 8*(lq & 1)) * 80 + (lq >> 1) * 16);
    const uint32_t boffW = (uint32_t)((warp_n*64 + lr + 8*(lq >> 1)) * 272 + (lq & 1) * 16);

    float acc[2][8][4];
    #pragma unroll
    for (int mt = 0; mt < 2; mt++)
        #pragma unroll
        for (int nt = 0; nt < 8; nt++)
            #pragma unroll
            for (int j = 0; j < 4; j++) acc[mt][nt][j] = 0.f;

    for (int kk = 0; kk < 4; kk++) {
        if (kk < 3) proj_loadA(X, row0, kk + 1, tid, xv);

        #pragma unroll
        for (int ks = 0; ks < 2; ks++) {
            const uint32_t kb = ks * 32;
            uint32_t ahi[2][4], alo[2][4];
            #pragma unroll
            for (int mt = 0; mt < 2; mt++) {
                LDSM_X4(ahi[mt], base + P_AHI + aoff + mt*16*80 + kb);
                LDSM_X4(alo[mt], base + P_ALO + aoff + mt*16*80 + kb);
            }
            uint32_t bhi[16], blo[16];
            #pragma unroll
            for (int np = 0; np < 4; np++) {
                const uint32_t wb = boffW + np*16*272 + kk*64 + kb;
                LDSM_X4(&bhi[np*4], base + P_WHI + wb);
                LDSM_X4(&blo[np*4], base + P_WLO + wb);
            }
            #pragma unroll
            for (int mt = 0; mt < 2; mt++)
                #pragma unroll
                for (int nt = 0; nt < 8; nt++) {
                    MMA_BF16(acc[mt][nt], ahi[mt], &bhi[nt*2]);
                    MMA_BF16(acc[mt][nt], ahi[mt], &blo[nt*2]);
                    MMA_BF16(acc[mt][nt], alo[mt], &bhi[nt*2]);
                }
        }

        if (kk < 3) {
            __syncthreads();
            proj_storeA(psm, tid, xv);
            __syncthreads();
        }
    }

    // ---- epilogue: bias, per-head norm, pack, smem transpose, coalesced STG
    __syncthreads();

    #pragma unroll
    for (int mt = 0; mt < 2; mt++) {
        const int ra = warp_m*32 + mt*16 + (lane >> 2);
        float y[8][4];
        float ssA0 = 0.f, ssA1 = 0.f, ssB0 = 0.f, ssB1 = 0.f;
        #pragma unroll
        for (int nt = 0; nt < 8; nt++) {
            const int o = nb + warp_n*64 + nt*8 + (lane & 3)*2;
            const float2 bv = *(const float2*)&bias[o];
            y[nt][0] = acc[mt][nt][0] + bv.x;
            y[nt][1] = acc[mt][nt][1] + bv.y;
            y[nt][2] = acc[mt][nt][2] + bv.x;
            y[nt][3] = acc[mt][nt][3] + bv.y;
            if (nt < 4) {
                ssA0 += y[nt][0]*y[nt][0] + y[nt][1]*y[nt][1];
                ssA1 += y[nt][2]*y[nt][2] + y[nt][3]*y[nt][3];
            } else {
                ssB0 += y[nt][0]*y[nt][0] + y[nt][1]*y[nt][1];
                ssB1 += y[nt][2]*y[nt][2] + y[nt][3]*y[nt][3];
            }
        }
        float scA0 = 1.f, scA1 = 1.f, scB0 = 1.f, scB1 = 1.f;
        if (NORM) {
            ssA0 += __shfl_xor_sync(0xffffffffu, ssA0, 1);
            ssA0 += __shfl_xor_sync(0xffffffffu, ssA0, 2);
            ssA1 += __shfl_xor_sync(0xffffffffu, ssA1, 1);
            ssA1 += __shfl_xor_sync(0xffffffffu, ssA1, 2);
            ssB0 += __shfl_xor_sync(0xffffffffu, ssB0, 1);
            ssB0 += __shfl_xor_sync(0xffffffffu, ssB0, 2);
            ssB1 += __shfl_xor_sync(0xffffffffu, ssB1, 1);
            ssB1 += __shfl_xor_sync(0xffffffffu, ssB1, 2);
            scA0 = rsqrtf(fmaxf(ssA0, 1e-24f));
            scA1 = rsqrtf(fmaxf(ssA1, 1e-24f));
            scB0 = rsqrtf(fmaxf(ssB0, 1e-24f));
            scB1 = rsqrtf(fmaxf(ssB1, 1e-24f));
        }
        #pragma unroll
        for (int nt = 0; nt < 8; nt++) {
            const int slot = warp_n*2 + (nt >> 2);
            const int dd   = (nt & 3)*8 + (lane & 3)*2;
            const float s0 = (nt < 4) ? scA0 : scB0;
            const float s1 = (nt < 4) ? scA1 : scB1;
            uint32_t hi, lo;
            pack_hilo(y[nt][0]*s0, y[nt][1]*s0, hi, lo);
            *(uint32_t*)(psm + ra*EPI_PITCH + slot*128 + dd*2)      = hi;
            *(uint32_t*)(psm + ra*EPI_PITCH + slot*128 + dd*2 + 64) = lo;
            pack_hilo(y[nt][2]*s1, y[nt][3]*s1, hi, lo);
            *(uint32_t*)(psm + (ra+8)*EPI_PITCH + slot*128 + dd*2)      = hi;
            *(uint32_t*)(psm + (ra+8)*EPI_PITCH + slot*128 + dd*2 + 64) = lo;
        }
    }
    __syncthreads();

    // cooperative coalesced copy: 128 rows x 4 slots x 8 uint4 (FULL 128B rows)
    const int hb = nb >> 5;
    #pragma unroll
    for (int i = 0; i < 16; i++) {
        int idx = tid + i * 256;              // 0..4095
        int r = idx >> 5, slot = (idx >> 3) & 3, u = idx & 7;
        uint4 val = *(uint4*)(psm + r*EPI_PITCH + slot*128 + u*16);
        const int grow = row0 + r;
        const int bb = grow / RPB, cc = grow - bb * RPB;
        *(uint4*)&Yp[(((long long)bb*NH + hb + slot) * RPB + cc) * 64 + u*8] = val;
    }
}

// ---------------- attention: full-mma, unified pitch-144 [hi|lo] rows -------
#define ATT_Q  0          // 64 rows x 144B (aliased by ORD after q-frag load)
#define ATT_K  9216       // 200 rows x 144B
#define ATT_V  38016      // 200 rows x 144B
#define ATT_PB 66816
#define ATT_RMX 67616
#define ATT_RSM 68128
#define ATT_ORD 0
#define ATT_SMEM 68640

__global__ __launch_bounds__(256, 2)
void att_mma(const float* __restrict__ pos_bias,
             float* __restrict__ att_out, int write_att)
{
    extern __shared__ char sm[];
    const uint32_t base = smem_u32(sm);
    float* spb  = (float*)(sm + ATT_PB);
    float* srmx = (float*)(sm + ATT_RMX);
    float* srsm = (float*)(sm + ATT_RSM);
    float* sord = (float*)(sm + ATT_ORD);

    const int bh = blockIdx.x;
    const int b  = bh >> 3;
    const int h  = bh & 7;
    const int tid  = threadIdx.x;
    const int wid  = tid >> 5;
    const int lane = tid & 31;
    const int warp_m = wid & 3;
    const int warp_n = wid >> 2;

    // ---- branch-free copy front-end: prepacked [hi|lo] rows ----
    #pragma unroll
    for (int i = 0; i < 2; i++) {
        int idx = tid + i * 256;              // 0..511
        int row = idx >> 3, part = idx & 7;
        uint4 val = make_uint4(0u, 0u, 0u, 0u);
        if (row < NT)
            val = *(const uint4*)&g_qp[((long long)bh*NT + row)*64 + part*8];
        *(uint4*)(sm + ATT_Q + row*144 + part*16) = val;
    }
    for (int idx = tid; idx < 1600; idx += 256) {
        int row = idx >> 3, part = idx & 7;
        *(uint4*)(sm + ATT_K + row*144 + part*16) =
            *(const uint4*)&g_kp[((long long)bh*WINDOW + row)*64 + part*8];
    }
    for (int idx = tid; idx < 1600; idx += 256) {
        int row = idx >> 3, part = idx & 7;
        *(uint4*)(sm + ATT_V + row*144 + part*16) =
            *(const uint4*)&g_vb[((long long)bh*WINDOW + row)*64 + part*8];
    }
    if (tid < WINDOW) spb[tid] = pos_bias[tid];
    __syncthreads();

    const int lr = lane & 7;
    const int lq = lane >> 3;
    const int nbase = warp_n * 104;

    // ---- q fragments (hi at +0/+32, lo at +64/+96) ----
    const uint32_t aoff = (uint32_t)((warp_m*16 + lr + 8*(lq & 1)) * 144 + (lq >> 1) * 16);
    uint32_t qhiF[2][4], qloF[2][4];
    LDSM_X4(qhiF[0], base + ATT_Q + aoff);
    LDSM_X4(qhiF[1], base + ATT_Q + aoff + 32);
    LDSM_X4(qloF[0], base + ATT_Q + aoff + 64);
    LDSM_X4(qloF[1], base + ATT_Q + aoff + 96);

    float S[13][4];
    #pragma unroll
    for (int nt = 0; nt < 13; nt++)
        #pragma unroll
        for (int j = 0; j < 4; j++) S[nt][j] = 0.f;

    const uint32_t boffK = (uint32_t)((nbase + lr + 8*(lq >> 1)) * 144 + (lq & 1) * 16);
    #pragma unroll
    for (int p = 0; p < 7; p++) {
        uint32_t Bh0[4], Bh1[4], Bl0[4], Bl1[4];
        LDSM_X4(Bh0, base + ATT_K + boffK + p*2304);
        LDSM_X4(Bh1, base + ATT_K + boffK + p*2304 + 32);
        LDSM_X4(Bl0, base + ATT_K + boffK + p*2304 + 64);
        LDSM_X4(Bl1, base + ATT_K + boffK + p*2304 + 96);
        #pragma unroll
        for (int s = 0; s < 2; s++) {
            const int nt = 2*p + s;
            if (nt > 12) break;
            MMA_BF16(S[nt], qhiF[0], &Bh0[s*2]);
            MMA_BF16(S[nt], qhiF[1], &Bh1[s*2]);
            MMA_BF16(S[nt], qhiF[0], &Bl0[s*2]);
            MMA_BF16(S[nt], qhiF[1], &Bl1[s*2]);
            MMA_BF16(S[nt], qloF[0], &Bh0[s*2]);
            MMA_BF16(S[nt], qloF[1], &Bh1[s*2]);
        }
    }

    const int r0 = warp_m*16 + (lane >> 2);
    float mx0 = -3e38f, mx1 = -3e38f;
    #pragma unroll
    for (int nt = 0; nt < 13; nt++) {
        if (warp_n == 1 && nt == 12) {
            S[nt][0] = S[nt][1] = S[nt][2] = S[nt][3] = -1e30f;
        } else {
            const int c = nbase + nt*8 + (lane & 3)*2;
            float2 pb2 = *(float2*)&spb[c];
            S[nt][0] += pb2.x; S[nt][1] += pb2.y;
            S[nt][2] += pb2.x; S[nt][3] += pb2.y;
        }
        mx0 = fmaxf(mx0, fmaxf(S[nt][0], S[nt][1]));
        mx1 = fmaxf(mx1, fmaxf(S[nt][2], S[nt][3]));
    }
    mx0 = fmaxf(mx0, __shfl_xor_sync(0xffffffffu, mx0, 1));
    mx0 = fmaxf(mx0, __shfl_xor_sync(0xffffffffu, mx0, 2));
    mx1 = fmaxf(mx1, __shfl_xor_sync(0xffffffffu, mx1, 1));
    mx1 = fmaxf(mx1, __shfl_xor_sync(0xffffffffu, mx1, 2));
    if ((lane & 3) == 0) {
        srmx[r0*2 + warp_n]     = mx0;
        srmx[(r0+8)*2 + warp_n] = mx1;
    }
    __syncthreads();
    mx0 = fmaxf(srmx[r0*2],     srmx[r0*2 + 1]);
    mx1 = fmaxf(srmx[(r0+8)*2], srmx[(r0+8)*2 + 1]);

    float sm0 = 0.f, sm1 = 0.f;
    #pragma unroll
    for (int nt = 0; nt < 13; nt++) {
        S[nt][0] = __expf(S[nt][0] - mx0);
        S[nt][1] = __expf(S[nt][1] - mx0);
        S[nt][2] = __expf(S[nt][2] - mx1);
        S[nt][3] = __expf(S[nt][3] - mx1);
        sm0 += S[nt][0] + S[nt][1];
        sm1 += S[nt][2] + S[nt][3];
    }
    sm0 += __shfl_xor_sync(0xffffffffu, sm0, 1);
    sm0 += __shfl_xor_sync(0xffffffffu, sm0, 2);
    sm1 += __shfl_xor_sync(0xffffffffu, sm1, 1);
    sm1 += __shfl_xor_sync(0xffffffffu, sm1, 2);
    if ((lane & 3) == 0) {
        srsm[r0*2 + warp_n]     = sm0;
        srsm[(r0+8)*2 + warp_n] = sm1;
    }
    __syncthreads();
    const float inv0 = 1.0f / (srsm[r0*2]     + srsm[r0*2 + 1]);
    const float inv1 = 1.0f / (srsm[(r0+8)*2] + srsm[(r0+8)*2 + 1]);
    #pragma unroll
    for (int nt = 0; nt < 13; nt++) {
        S[nt][0] *= inv0; S[nt][1] *= inv0;
        S[nt][2] *= inv1; S[nt][3] *= inv1;
    }

    if (write_att) {
        float* ab = att_out + (long long)bh * NT * WINDOW;
        #pragma unroll
        for (int nt = 0; nt < 13; nt++) {
            if (warp_n == 1 && nt == 12) continue;
            const int c = nbase + nt*8 + (lane & 3)*2;
            if (r0 < NT)
                *(float2*)&ab[r0*WINDOW + c]     = make_float2(S[nt][0], S[nt][1]);
            if (r0 + 8 < NT)
                *(float2*)&ab[(r0+8)*WINDOW + c] = make_float2(S[nt][2], S[nt][3]);
        }
    }

    // ---- AV mma (V^T fragments via ldmatrix.trans; hi/lo at +0/+64) ----
    float O[4][4];
    #pragma unroll
    for (int j = 0; j < 4; j++)
        #pragma unroll
        for (int i = 0; i < 4; i++) O[j][i] = 0.f;

    const uint32_t voff = (uint32_t)(((lq & 1)*8 + lr) * 144 + (lq >> 1) * 16);
    #pragma unroll
    for (int q = 0; q < 7; q++) {
        if (q == 6 && warp_n == 1) break;
        const int kc = nbase + q*16;
        uint32_t vh0[4], vh1[4], vl0[4], vl1[4];
        LDSM_X4_T(vh0, base + ATT_V + voff + kc*144);
        LDSM_X4_T(vh1, base + ATT_V + voff + kc*144 + 32);
        LDSM_X4_T(vl0, base + ATT_V + voff + kc*144 + 64);
        LDSM_X4_T(vl1, base + ATT_V + voff + kc*144 + 96);

        uint32_t ahi[4], alo[4];
        const int tA = 2*q, tB = 2*q + 1;
        pack_hilo(S[tA][0], S[tA][1], ahi[0], alo[0]);
        pack_hilo(S[tA][2], S[tA][3], ahi[1], alo[1]);
        if (tB <= 12) {
            pack_hilo(S[tB][0], S[tB][1], ahi[2], alo[2]);
            pack_hilo(S[tB][2], S[tB][3], ahi[3], alo[3]);
        } else {
            ahi[2] = ahi[3] = alo[2] = alo[3] = 0u;
        }
        MMA_BF16(O[0], ahi, &vh0[0]); MMA_BF16(O[0], ahi, &vl0[0]); MMA_BF16(O[0], alo, &vh0[0]);
        MMA_BF16(O[1], ahi, &vh0[2]); MMA_BF16(O[1], ahi, &vl0[2]); MMA_BF16(O[1], alo, &vh0[2]);
        MMA_BF16(O[2], ahi, &vh1[0]); MMA_BF16(O[2], ahi, &vl1[0]); MMA_BF16(O[2], alo, &vh1[0]);
        MMA_BF16(O[3], ahi, &vh1[2]); MMA_BF16(O[3], ahi, &vl1[2]); MMA_BF16(O[3], alo, &vh1[2]);
    }

    // ---- combine the 2 N-half partials (sord aliases Q region), write g_oh
    __syncthreads();   // all q-fragment/K/V reads complete before ORD overwrite
    if (warp_n == 0) {
        #pragma unroll
        for (int j = 0; j < 4; j++) {
            const int d = j*8 + (lane & 3)*2;
            *(float2*)&sord[r0*36 + d]     = make_float2(O[j][0], O[j][1]);
            *(float2*)&sord[(r0+8)*36 + d] = make_float2(O[j][2], O[j][3]);
        }
    }
    __syncthreads();
    if (warp_n == 1) {
        #pragma unroll
        for (int j = 0; j < 4; j++) {
            const int d = j*8 + (lane & 3)*2;
            if (r0 < NT) {
                float2 p = *(float2*)&sord[r0*36 + d];
                *(float2*)&g_oh[((long long)b*NT + r0)*256 + h*32 + d] =
                    make_float2(p.x + O[j][0], p.y + O[j][1]);
            }
            if (r0 + 8 < NT) {
                float2 p = *(float2*)&sord[(r0+8)*36 + d];
                *(float2*)&g_oh[((long long)b*NT + r0 + 8)*256 + h*32 + d] =
                    make_float2(p.x + O[j][2], p.y + O[j][3]);
            }
        }
    }
}

// ---------------- final projection: out = oh @ R^T + Rb --------------------
__global__ __launch_bounds__(256)
void out_kernel(const float* __restrict__ Rb, float* __restrict__ out)
{
    __shared__ float sx[25 * 256];
    __shared__ float pbuf[25 * 128];
    const int row0 = blockIdx.x * 25;

    const float4* xg = (const float4*)(g_oh + (long long)row0 * 256);
    float4* sx4 = (float4*)sx;
    #pragma unroll
    for (int i = 0; i < 7; i++) {
        int idx = threadIdx.x + i * 256;
        if (idx < 1600) sx4[idx] = xg[idx];
    }
    __syncthreads();

    const int e    = threadIdx.x & 127;
    const int half = threadIdx.x >> 7;
    float2 acc[25];
    #pragma unroll
    for (int r = 0; r < 25; r++) acc[r] = make_float2(0.f, 0.f);

    const int k0 = half * 128;
    for (int k = 0; k < 128; k += 4) {
        const int kk = k0 + k;
        float w0 = g_rt[(kk+0)*128 + e];
        float w1 = g_rt[(kk+1)*128 + e];
        float w2 = g_rt[(kk+2)*128 + e];
        float w3 = g_rt[(kk+3)*128 + e];
        float2 wab = make_float2(w0, w1), wcd = make_float2(w2, w3);
        #pragma unroll
        for (int r = 0; r < 25; r++) {
            float4 x4 = *(const float4*)&sx[r*256 + kk];
            acc[r] = ffma2(make_float2(x4.x, x4.y), wab, acc[r]);
            acc[r] = ffma2(make_float2(x4.z, x4.w), wcd, acc[r]);
        }
    }

    if (half == 1) {
        #pragma unroll
        for (int r = 0; r < 25; r++) pbuf[r*128 + e] = acc[r].x + acc[r].y;
    }
    __syncthreads();
    if (half == 0) {
        const float bo = Rb[e];
        #pragma unroll
        for (int r = 0; r < 25; r++) {
            out[(long long)(row0 + r) * 128 + e] =
                acc[r].x + acc[r].y + pbuf[r*128 + e] + bo;
        }
    }
}

// ---------------- launch ----------------------------------------------------
extern "C" void kernel_launch(void* const* d_in, const int* in_sizes, int n_in,
                              void* d_out, int out_size)
{
    const float* queries  = (const float*)d_in[0];
    const float* keys     = (const float*)d_in[1];
    const float* values   = (const float*)d_in[2];
    const float* At_w     = (const float*)d_in[3];
    const float* At_b     = (const float*)d_in[4];
    const float* Ac_w     = (const float*)d_in[5];
    const float* Ac_b     = (const float*)d_in[6];
    const float* Bc_w     = (const float*)d_in[7];
    const float* Bc_b     = (const float*)d_in[8];
    const float* pos_bias = (const float*)d_in[9];
    const float* R_w      = (const float*)d_in[10];
    const float* R_b      = (const float*)d_in[11];
    float* out = (float*)d_out;

    cudaFuncSetAttribute(att_mma,
        cudaFuncAttributeMaxDynamicSharedMemorySize, ATT_SMEM);
    cudaFuncSetAttribute(proj_mma<NT, 0, 1>,
        cudaFuncAttributeMaxDynamicSharedMemorySize, PROJ_SMEM);
    cudaFuncSetAttribute(proj_mma<WINDOW, 1, 1>,
        cudaFuncAttributeMaxDynamicSharedMemorySize, PROJ_SMEM);
    cudaFuncSetAttribute(proj_mma<WINDOW, 2, 0>,
        cudaFuncAttributeMaxDynamicSharedMemorySize, PROJ_SMEM);

    prep_w<<<128, 256>>>(At_w, Ac_w, Bc_w, R_w);

    proj_mma<NT,     0, 1><<<dim3(NB*NT/128,     2), 256, PROJ_SMEM>>>(queries, At_b, 0);
    proj_mma<WINDOW, 1, 1><<<dim3(NB*WINDOW/128, 2), 256, PROJ_SMEM>>>(keys,    Ac_b, 1);
    proj_mma<WINDOW, 2, 0><<<dim3(NB*WINDOW/128, 2), 256, PROJ_SMEM>>>(values,  Bc_b, 2);

    const long long need = (long long)OUT_ELEMS + (long long)ATT_ELEMS;
    const int write_att = ((long long)out_size >= need) ? 1 : 0;
    att_mma<<<NB*NH, 256, ATT_SMEM>>>(pos_bias, out + OUT_ELEMS, write_att);

    out_kernel<<<NB*NT/25, 256>>>(R_b, out);
}

// round 17
// speedup vs baseline: 1.2259x; 1.2259x over previous
#include <cuda_runtime.h>
#include <cuda_bf16.h>
#include <math.h>
#include <stdint.h>

#define EMB 128
#define WINDOW 200
#define DK 32
#define NH 8
#define NT 50
#define NB 1024

#define OUT_ELEMS (NB*NT*EMB)          // 6,553,600
#define ATT_ELEMS (NB*NH*NT*WINDOW)    // 81,920,000

// ---------------- scratch (device globals; no runtime allocation) ----------
__device__ float g_qh[NB*NH*NT*DK];       // q projection  (b,h,t,d)
__device__ float g_kh[NB*NH*WINDOW*DK];   // k projection  (b,h,c,d)
__device__ float g_vp[NB*NH*WINDOW*DK];   // v projection  (b,h,c,d)
__device__ float g_oh[NB*NT*NH*DK];       // out heads     (b,t,h*32+d)
__device__ float g_rt [256*EMB];          // R_w transposed:  [o][e]
__device__ __nv_bfloat16 g_wbhi[3*256*EMB];  // W hi bf16, [o][k]
__device__ __nv_bfloat16 g_wblo[3*256*EMB];  // W lo residual bf16

// ================= helpers ==================================================
__device__ __forceinline__ uint32_t smem_u32(const void* p) {
    uint32_t a;
    asm("{ .reg .u64 t; cvta.to.shared.u64 t, %1; cvt.u32.u64 %0, t; }"
        : "=r"(a) : "l"(p));
    return a;
}

__device__ __forceinline__ float2 ffma2(float2 a, float2 b, float2 c) {
    unsigned long long au, bu, cu, du;
    asm("mov.b64 %0, {%1, %2};" : "=l"(au) : "f"(a.x), "f"(a.y));
    asm("mov.b64 %0, {%1, %2};" : "=l"(bu) : "f"(b.x), "f"(b.y));
    asm("mov.b64 %0, {%1, %2};" : "=l"(cu) : "f"(c.x), "f"(c.y));
    asm("fma.rn.f32x2 %0, %1, %2, %3;" : "=l"(du) : "l"(au), "l"(bu), "l"(cu));
    float2 r;
    asm("mov.b64 {%0, %1}, %2;" : "=f"(r.x), "=f"(r.y) : "l"(du));
    return r;
}

#define LDSM_X4(d, addr) \
    asm volatile("ldmatrix.sync.aligned.m8n8.x4.shared.b16 {%0,%1,%2,%3}, [%4];" \
        : "=r"((d)[0]), "=r"((d)[1]), "=r"((d)[2]), "=r"((d)[3]) : "r"(addr))

#define LDSM_X4_T(d, addr) \
    asm volatile("ldmatrix.sync.aligned.m8n8.x4.trans.shared.b16 {%0,%1,%2,%3}, [%4];" \
        : "=r"((d)[0]), "=r"((d)[1]), "=r"((d)[2]), "=r"((d)[3]) : "r"(addr))

#define MMA_BF16(c, a, b) \
    asm volatile("mma.sync.aligned.m16n8k16.row.col.f32.bf16.bf16.f32 " \
        "{%0,%1,%2,%3}, {%4,%5,%6,%7}, {%8,%9}, {%0,%1,%2,%3};" \
        : "+f"((c)[0]), "+f"((c)[1]), "+f"((c)[2]), "+f"((c)[3]) \
        : "r"((a)[0]), "r"((a)[1]), "r"((a)[2]), "r"((a)[3]), \
          "r"((b)[0]), "r"((b)[1]))

// streaming (evict-first) 8-byte global store
__device__ __forceinline__ void stg_cs_f2(float* p, float2 v) {
    asm volatile("st.global.cs.v2.f32 [%0], {%1, %2};"
                 :: "l"(p), "f"(v.x), "f"(v.y) : "memory");
}

__device__ __forceinline__ void pack_hilo(float x0, float x1,
                                          uint32_t& hi, uint32_t& lo) {
    __nv_bfloat162 h = __floats2bfloat162_rn(x0, x1);
    float r0 = x0 - __low2float(h), r1 = x1 - __high2float(h);
    __nv_bfloat162 l = __floats2bfloat162_rn(r0, r1);
    uint32_t hu, lu;
    memcpy(&hu, &h, 4); memcpy(&lu, &l, 4);
    hi = hu; lo = lu;
}

// ---------------- prep: W bf16 hi/lo split + R transpose --------------------
__global__ void prep_w(const float* __restrict__ At, const float* __restrict__ Ac,
                       const float* __restrict__ Bc, const float* __restrict__ R)
{
    int i = blockIdx.x * 256 + threadIdx.x;
    if (i < 32768) {
        const float* srcs[3] = {At, Ac, Bc};
        #pragma unroll
        for (int m = 0; m < 3; m++) {
            float a  = srcs[m][i];
            __nv_bfloat16 h = __float2bfloat16_rn(a);
            float lo = a - __bfloat162float(h);
            g_wbhi[m*32768 + i] = h;
            g_wblo[m*32768 + i] = __float2bfloat16_rn(lo);
        }
        int e = i >> 8, oo = i & 255;
        g_rt[oo*128 + e] = R[i];
    }
}

// ---------------- tensor-core projection (W-resident, 2 blocks/SM) ----------
#define P_AHI 0
#define P_ALO 10240
#define P_WHI 20480
#define P_WLO 55296
#define PROJ_SMEM 90112

__device__ __forceinline__ void proj_loadA(
    const float* __restrict__ X, int row0, int kk, int tid, float4* xv)
{
    #pragma unroll
    for (int i = 0; i < 4; i++) {
        int idx = tid + i * 256;
        int r = idx >> 3, f4 = idx & 7;
        xv[i] = *(const float4*)(X + (long long)(row0 + r) * EMB + kk*32 + f4*4);
    }
}

__device__ __forceinline__ void proj_storeA(
    char* psm, int tid, const float4* xv)
{
    #pragma unroll
    for (int i = 0; i < 4; i++) {
        int idx = tid + i * 256;
        int r = idx >> 3, f4 = idx & 7;
        float4 x = xv[i];
        uint32_t h0, l0, h1, l1;
        pack_hilo(x.x, x.y, h0, l0);
        pack_hilo(x.z, x.w, h1, l1);
        *(uint2*)(psm + P_AHI + r*80 + f4*8) = make_uint2(h0, h1);
        *(uint2*)(psm + P_ALO + r*80 + f4*8) = make_uint2(l0, l1);
    }
}

template<int RPB, int DST>
__global__ __launch_bounds__(256, 2)
void proj_mma(const float* __restrict__ X, const float* __restrict__ bias, int widx)
{
    extern __shared__ char psm[];
    const uint32_t base = smem_u32(psm);

    float* __restrict__ Y = (DST == 0) ? g_qh : (DST == 1) ? g_kh : g_vp;
    const __nv_bfloat16* __restrict__ Whi = g_wbhi + widx * 32768;
    const __nv_bfloat16* __restrict__ Wlo = g_wblo + widx * 32768;

    const int tid    = threadIdx.x;
    const int wid    = tid >> 5;
    const int lane   = tid & 31;
    const int warp_m = wid & 3;
    const int warp_n = wid >> 2;
    const int row0   = blockIdx.x * 128;
    const int nb     = blockIdx.y * 128;

    // ---- prologue: full W half into smem (pitch 272B, conflict-free) ----
    #pragma unroll
    for (int i = 0; i < 8; i++) {
        int idx = tid + i * 256;           // 0..2047: r = idx>>4, g = idx&15
        int r = idx >> 4, g = idx & 15;
        const long long src = (long long)(nb + r) * EMB + g*8;
        *(uint4*)(psm + P_WHI + r*272 + g*16) = *(const uint4*)&Whi[src];
        *(uint4*)(psm + P_WLO + r*272 + g*16) = *(const uint4*)&Wlo[src];
    }

    float4 xv[4];
    proj_loadA(X, row0, 0, tid, xv);
    proj_storeA(psm, tid, xv);
    __syncthreads();

    const int lr = lane & 7;
    const int lq = lane >> 3;
    const uint32_t aoff  = (uint32_t)((warp_m*32 + lr + 8*(lq & 1)) * 80 + (lq >> 1) * 16);
    const uint32_t boffW = (uint32_t)((warp_n*64 + lr + 8*(lq >> 1)) * 272 + (lq & 1) * 16);

    float acc[2][8][4];
    #pragma unroll
    for (int mt = 0; mt < 2; mt++)
        #pragma unroll
        for (int nt = 0; nt < 8; nt++)
            #pragma unroll
            for (int j = 0; j < 4; j++) acc[mt][nt][j] = 0.f;

    for (int kk = 0; kk < 4; kk++) {
        if (kk < 3) proj_loadA(X, row0, kk + 1, tid, xv);   // LDGs fly under MMA

        #pragma unroll
        for (int ks = 0; ks < 2; ks++) {
            const uint32_t kb = ks * 32;
            uint32_t ahi[2][4], alo[2][4];
            #pragma unroll
            for (int mt = 0; mt < 2; mt++) {
                LDSM_X4(ahi[mt], base + P_AHI + aoff + mt*16*80 + kb);
                LDSM_X4(alo[mt], base + P_ALO + aoff + mt*16*80 + kb);
            }
            uint32_t bhi[16], blo[16];
            #pragma unroll
            for (int np = 0; np < 4; np++) {
                const uint32_t wb = boffW + np*16*272 + kk*64 + kb;
                LDSM_X4(&bhi[np*4], base + P_WHI + wb);
                LDSM_X4(&blo[np*4], base + P_WLO + wb);
            }
            #pragma unroll
            for (int mt = 0; mt < 2; mt++)
                #pragma unroll
                for (int nt = 0; nt < 8; nt++) {
                    MMA_BF16(acc[mt][nt], ahi[mt], &bhi[nt*2]);
                    MMA_BF16(acc[mt][nt], ahi[mt], &blo[nt*2]);
                    MMA_BF16(acc[mt][nt], alo[mt], &bhi[nt*2]);
                }
        }

        if (kk < 3) {
            __syncthreads();                 // all warps done reading A(kk)
            proj_storeA(psm, tid, xv);       // overwrite with A(kk+1)
            __syncthreads();
        }
    }

    // ---- epilogue: + bias, scatter to (b, h, seq, d) fp32 ----
    #pragma unroll
    for (int mt = 0; mt < 2; mt++) {
        const int r0 = row0 + warp_m*32 + mt*16 + (lane >> 2);
        const int r1 = r0 + 8;
        const int bb0 = r0 / RPB, cc0 = r0 - bb0 * RPB;
        const int bb1 = r1 / RPB, cc1 = r1 - bb1 * RPB;
        #pragma unroll
        for (int nt = 0; nt < 8; nt++) {
            const int o = nb + warp_n*64 + nt*8 + (lane & 3)*2;
            const int h = o >> 5, d = o & 31;
            const float2 bv = *(const float2*)&bias[o];
            float2 v0 = make_float2(acc[mt][nt][0] + bv.x, acc[mt][nt][1] + bv.y);
            float2 v1 = make_float2(acc[mt][nt][2] + bv.x, acc[mt][nt][3] + bv.y);
            *(float2*)&Y[(((long long)bb0 * NH + h) * RPB + cc0) * DK + d] = v0;
            *(float2*)&Y[(((long long)bb1 * NH + h) * RPB + cc1) * DK + d] = v1;
        }
    }
}

// ---------------- attention: full-mma, fragment-resident --------------------
#define ATT_QHI 0
#define ATT_QLO 5120
#define ATT_KHI 10240
#define ATT_KLO 28160
#define ATT_VHI 46080
#define ATT_VLO 62720
#define ATT_PB  79360
#define ATT_RMX 80160
#define ATT_RSM 80672
#define ATT_ORD 81184
#define ATT_SMEM 90400

__global__ __launch_bounds__(256, 2)
void att_mma(const float* __restrict__ pos_bias,
             float* __restrict__ att_out, int write_att)
{
    extern __shared__ char sm[];
    const uint32_t base = smem_u32(sm);
    __nv_bfloat16* smQhi = (__nv_bfloat16*)(sm + ATT_QHI);
    __nv_bfloat16* smQlo = (__nv_bfloat16*)(sm + ATT_QLO);
    __nv_bfloat16* smKhi = (__nv_bfloat16*)(sm + ATT_KHI);
    __nv_bfloat16* smKlo = (__nv_bfloat16*)(sm + ATT_KLO);
    __nv_bfloat16* smVhi = (__nv_bfloat16*)(sm + ATT_VHI);
    __nv_bfloat16* smVlo = (__nv_bfloat16*)(sm + ATT_VLO);
    float* spb  = (float*)(sm + ATT_PB);
    float* srmx = (float*)(sm + ATT_RMX);
    float* srsm = (float*)(sm + ATT_RSM);
    float* sord = (float*)(sm + ATT_ORD);

    const int bh = blockIdx.x;
    const int b  = bh >> 3;
    const int h  = bh & 7;
    const int tid  = threadIdx.x;
    const int wid  = tid >> 5;
    const int lane = tid & 31;
    const int warp_m = wid & 3;
    const int warp_n = wid >> 2;

    if (tid < 64) {
        float4 qr[8];
        float sc = 0.f;
        if (tid < NT) {
            const float4* qg = (const float4*)(g_qh + ((long long)bh*NT + tid)*DK);
            float ss = 0.f;
            #pragma unroll
            for (int j = 0; j < 8; j++) {
                qr[j] = qg[j];
                ss += qr[j].x*qr[j].x + qr[j].y*qr[j].y + qr[j].z*qr[j].z + qr[j].w*qr[j].w;
            }
            sc = rsqrtf(fmaxf(ss, 1e-24f));
        } else {
            #pragma unroll
            for (int j = 0; j < 8; j++) qr[j] = make_float4(0.f,0.f,0.f,0.f);
        }
        #pragma unroll
        for (int j = 0; j < 8; j++) {
            uint32_t h0,l0,h1,l1;
            pack_hilo(qr[j].x*sc, qr[j].y*sc, h0, l0);
            pack_hilo(qr[j].z*sc, qr[j].w*sc, h1, l1);
            *(uint2*)&smQhi[tid*40 + j*4] = make_uint2(h0, h1);
            *(uint2*)&smQlo[tid*40 + j*4] = make_uint2(l0, l1);
        }
    }
    if (tid < WINDOW) {
        const float4* kg = (const float4*)(g_kh + ((long long)bh*WINDOW + tid)*DK);
        float4 kr[8];
        float ss = 0.f;
        #pragma unroll
        for (int j = 0; j < 8; j++) {
            kr[j] = kg[j];
            ss += kr[j].x*kr[j].x + kr[j].y*kr[j].y + kr[j].z*kr[j].z + kr[j].w*kr[j].w;
        }
        const float sc = rsqrtf(fmaxf(ss, 1e-24f));
        #pragma unroll
        for (int j = 0; j < 8; j++) {
            uint32_t h0,l0,h1,l1;
            pack_hilo(kr[j].x*sc, kr[j].y*sc, h0, l0);
            pack_hilo(kr[j].z*sc, kr[j].w*sc, h1, l1);
            *(uint2*)&smKhi[tid*40 + j*4] = make_uint2(h0, h1);
            *(uint2*)&smKlo[tid*40 + j*4] = make_uint2(l0, l1);
        }
        spb[tid] = pos_bias[tid];
    }
    {
        const float4* vg = (const float4*)(g_vp + (long long)bh*WINDOW*DK);
        #pragma unroll
        for (int i = 0; i < 7; i++) {
            int idx = tid + i * 256;
            if (idx < 1600) {
                int c = idx >> 3, dg = idx & 7;
                float4 x = vg[idx];
                uint32_t h0,l0,h1,l1;
                pack_hilo(x.x, x.y, h0, l0);
                pack_hilo(x.z, x.w, h1, l1);
                *(uint2*)&smVhi[c*40 + dg*4] = make_uint2(h0, h1);
                *(uint2*)&smVlo[c*40 + dg*4] = make_uint2(l0, l1);
            }
        }
    }
    __syncthreads();

    const int lr = lane & 7;
    const int lq = lane >> 3;
    const int nbase = warp_n * 104;

    const uint32_t aoff = (uint32_t)((warp_m*16 + lr + 8*(lq & 1)) * 80 + (lq >> 1) * 16);
    uint32_t qhiF[2][4], qloF[2][4];
    LDSM_X4(qhiF[0], base + ATT_QHI + aoff);
    LDSM_X4(qhiF[1], base + ATT_QHI + aoff + 32);
    LDSM_X4(qloF[0], base + ATT_QLO + aoff);
    LDSM_X4(qloF[1], base + ATT_QLO + aoff + 32);

    float S[13][4];
    #pragma unroll
    for (int nt = 0; nt < 13; nt++)
        #pragma unroll
        for (int j = 0; j < 4; j++) S[nt][j] = 0.f;

    const uint32_t boffK = (uint32_t)((nbase + lr + 8*(lq >> 1)) * 80 + (lq & 1) * 16);
    #pragma unroll
    for (int p = 0; p < 7; p++) {
        uint32_t Bh0[4], Bh1[4], Bl0[4], Bl1[4];
        LDSM_X4(Bh0, base + ATT_KHI + boffK + p*16*80);
        LDSM_X4(Bh1, base + ATT_KHI + boffK + p*16*80 + 32);
        LDSM_X4(Bl0, base + ATT_KLO + boffK + p*16*80);
        LDSM_X4(Bl1, base + ATT_KLO + boffK + p*16*80 + 32);
        #pragma unroll
        for (int s = 0; s < 2; s++) {
            const int nt = 2*p + s;
            if (nt > 12) break;
            MMA_BF16(S[nt], qhiF[0], &Bh0[s*2]);
            MMA_BF16(S[nt], qhiF[1], &Bh1[s*2]);
            MMA_BF16(S[nt], qhiF[0], &Bl0[s*2]);
            MMA_BF16(S[nt], qhiF[1], &Bl1[s*2]);
            MMA_BF16(S[nt], qloF[0], &Bh0[s*2]);
            MMA_BF16(S[nt], qloF[1], &Bh1[s*2]);
        }
    }

    const int r0 = warp_m*16 + (lane >> 2);
    float mx0 = -3e38f, mx1 = -3e38f;
    #pragma unroll
    for (int nt = 0; nt < 13; nt++) {
        if (warp_n == 1 && nt == 12) {
            S[nt][0] = S[nt][1] = S[nt][2] = S[nt][3] = -1e30f;
        } else {
            const int c = nbase + nt*8 + (lane & 3)*2;
            float2 pb2 = *(float2*)&spb[c];
            S[nt][0] += pb2.x; S[nt][1] += pb2.y;
            S[nt][2] += pb2.x; S[nt][3] += pb2.y;
        }
        mx0 = fmaxf(mx0, fmaxf(S[nt][0], S[nt][1]));
        mx1 = fmaxf(mx1, fmaxf(S[nt][2], S[nt][3]));
    }
    mx0 = fmaxf(mx0, __shfl_xor_sync(0xffffffffu, mx0, 1));
    mx0 = fmaxf(mx0, __shfl_xor_sync(0xffffffffu, mx0, 2));
    mx1 = fmaxf(mx1, __shfl_xor_sync(0xffffffffu, mx1, 1));
    mx1 = fmaxf(mx1, __shfl_xor_sync(0xffffffffu, mx1, 2));
    if ((lane & 3) == 0) {
        srmx[r0*2 + warp_n]     = mx0;
        srmx[(r0+8)*2 + warp_n] = mx1;
    }
    __syncthreads();
    mx0 = fmaxf(srmx[r0*2],     srmx[r0*2 + 1]);
    mx1 = fmaxf(srmx[(r0+8)*2], srmx[(r0+8)*2 + 1]);

    float sm0 = 0.f, sm1 = 0.f;
    #pragma unroll
    for (int nt = 0; nt < 13; nt++) {
        S[nt][0] = __expf(S[nt][0] - mx0);
        S[nt][1] = __expf(S[nt][1] - mx0);
        S[nt][2] = __expf(S[nt][2] - mx1);
        S[nt][3] = __expf(S[nt][3] - mx1);
        sm0 += S[nt][0] + S[nt][1];
        sm1 += S[nt][2] + S[nt][3];
    }
    sm0 += __shfl_xor_sync(0xffffffffu, sm0, 1);
    sm0 += __shfl_xor_sync(0xffffffffu, sm0, 2);
    sm1 += __shfl_xor_sync(0xffffffffu, sm1, 1);
    sm1 += __shfl_xor_sync(0xffffffffu, sm1, 2);
    if ((lane & 3) == 0) {
        srsm[r0*2 + warp_n]     = sm0;
        srsm[(r0+8)*2 + warp_n] = sm1;
    }
    __syncthreads();
    const float inv0 = 1.0f / (srsm[r0*2]     + srsm[r0*2 + 1]);
    const float inv1 = 1.0f / (srsm[(r0+8)*2] + srsm[(r0+8)*2 + 1]);
    #pragma unroll
    for (int nt = 0; nt < 13; nt++) {
        S[nt][0] *= inv0; S[nt][1] *= inv0;
        S[nt][2] *= inv1; S[nt][3] *= inv1;
    }

    if (write_att) {
        float* ab = att_out + (long long)bh * NT * WINDOW;
        #pragma unroll
        for (int nt = 0; nt < 13; nt++) {
            if (warp_n == 1 && nt == 12) continue;
            const int c = nbase + nt*8 + (lane & 3)*2;
            if (r0 < NT)
                stg_cs_f2(&ab[r0*WINDOW + c],     make_float2(S[nt][0], S[nt][1]));
            if (r0 + 8 < NT)
                stg_cs_f2(&ab[(r0+8)*WINDOW + c], make_float2(S[nt][2], S[nt][3]));
        }
    }

    float O[4][4];
    #pragma unroll
    for (int j = 0; j < 4; j++)
        #pragma unroll
        for (int i = 0; i < 4; i++) O[j][i] = 0.f;

    const uint32_t voff = (uint32_t)(((lq & 1)*8 + lr) * 80 + (lq >> 1) * 16);
    #pragma unroll
    for (int q = 0; q < 7; q++) {
        if (q == 6 && warp_n == 1) break;
        const int kc = nbase + q*16;
        uint32_t vh0[4], vh1[4], vl0[4], vl1[4];
        LDSM_X4_T(vh0, base + ATT_VHI + voff + kc*80);
        LDSM_X4_T(vh1, base + ATT_VHI + voff + kc*80 + 32);
        LDSM_X4_T(vl0, base + ATT_VLO + voff + kc*80);
        LDSM_X4_T(vl1, base + ATT_VLO + voff + kc*80 + 32);

        uint32_t ahi[4], alo[4];
        const int tA = 2*q, tB = 2*q + 1;
        pack_hilo(S[tA][0], S[tA][1], ahi[0], alo[0]);
        pack_hilo(S[tA][2], S[tA][3], ahi[1], alo[1]);
        if (tB <= 12) {
            pack_hilo(S[tB][0], S[tB][1], ahi[2], alo[2]);
            pack_hilo(S[tB][2], S[tB][3], ahi[3], alo[3]);
        } else {
            ahi[2] = ahi[3] = alo[2] = alo[3] = 0u;
        }
        MMA_BF16(O[0], ahi, &vh0[0]); MMA_BF16(O[0], ahi, &vl0[0]); MMA_BF16(O[0], alo, &vh0[0]);
        MMA_BF16(O[1], ahi, &vh0[2]); MMA_BF16(O[1], ahi, &vl0[2]); MMA_BF16(O[1], alo, &vh0[2]);
        MMA_BF16(O[2], ahi, &vh1[0]); MMA_BF16(O[2], ahi, &vl1[0]); MMA_BF16(O[2], alo, &vh1[0]);
        MMA_BF16(O[3], ahi, &vh1[2]); MMA_BF16(O[3], ahi, &vl1[2]); MMA_BF16(O[3], alo, &vh1[2]);
    }

    if (warp_n == 0) {
        #pragma unroll
        for (int j = 0; j < 4; j++) {
            const int d = j*8 + (lane & 3)*2;
            *(float2*)&sord[r0*36 + d]     = make_float2(O[j][0], O[j][1]);
            *(float2*)&sord[(r0+8)*36 + d] = make_float2(O[j][2], O[j][3]);
        }
    }
    __syncthreads();
    if (warp_n == 1) {
        #pragma unroll
        for (int j = 0; j < 4; j++) {
            const int d = j*8 + (lane & 3)*2;
            if (r0 < NT) {
                float2 p = *(float2*)&sord[r0*36 + d];
                *(float2*)&g_oh[((long long)b*NT + r0)*256 + h*32 + d] =
                    make_float2(p.x + O[j][0], p.y + O[j][1]);
            }
            if (r0 + 8 < NT) {
                float2 p = *(float2*)&sord[(r0+8)*36 + d];
                *(float2*)&g_oh[((long long)b*NT + r0 + 8)*256 + h*32 + d] =
                    make_float2(p.x + O[j][2], p.y + O[j][3]);
            }
        }
    }
}

// ---------------- final projection: out = oh @ R^T + Rb --------------------
__global__ __launch_bounds__(256, 2)
void out_kernel(const float* __restrict__ Rb, float* __restrict__ out)
{
    __shared__ float sx[25 * 256];
    __shared__ float pbuf[25 * 128];
    const int row0 = blockIdx.x * 25;

    const float4* xg = (const float4*)(g_oh + (long long)row0 * 256);
    float4* sx4 = (float4*)sx;
    #pragma unroll
    for (int i = 0; i < 7; i++) {
        int idx = threadIdx.x + i * 256;
        if (idx < 1600) sx4[idx] = xg[idx];
    }
    __syncthreads();

    const int e    = threadIdx.x & 127;
    const int half = threadIdx.x >> 7;
    float2 acc[25];
    #pragma unroll
    for (int r = 0; r < 25; r++) acc[r] = make_float2(0.f, 0.f);

    const int k0 = half * 128;
    for (int k = 0; k < 128; k += 4) {
        const int kk = k0 + k;
        float w0 = g_rt[(kk+0)*128 + e];
        float w1 = g_rt[(kk+1)*128 + e];
        float w2 = g_rt[(kk+2)*128 + e];
        float w3 = g_rt[(kk+3)*128 + e];
        float2 wab = make_float2(w0, w1), wcd = make_float2(w2, w3);
        #pragma unroll
        for (int r = 0; r < 25; r++) {
            float4 x4 = *(const float4*)&sx[r*256 + kk];
            acc[r] = ffma2(make_float2(x4.x, x4.y), wab, acc[r]);
            acc[r] = ffma2(make_float2(x4.z, x4.w), wcd, acc[r]);
        }
    }

    if (half == 1) {
        #pragma unroll
        for (int r = 0; r < 25; r++) pbuf[r*128 + e] = acc[r].x + acc[r].y;
    }
    __syncthreads();
    if (half == 0) {
        const float bo = Rb[e];
        #pragma unroll
        for (int r = 0; r < 25; r++) {
            out[(long long)(row0 + r) * 128 + e] =
                acc[r].x + acc[r].y + pbuf[r*128 + e] + bo;
        }
    }
}

// ---------------- launch ----------------------------------------------------
extern "C" void kernel_launch(void* const* d_in, const int* in_sizes, int n_in,
                              void* d_out, int out_size)
{
    const float* queries  = (const float*)d_in[0];
    const float* keys     = (const float*)d_in[1];
    const float* values   = (const float*)d_in[2];
    const float* At_w     = (const float*)d_in[3];
    const float* At_b     = (const float*)d_in[4];
    const float* Ac_w     = (const float*)d_in[5];
    const float* Ac_b     = (const float*)d_in[6];
    const float* Bc_w     = (const float*)d_in[7];
    const float* Bc_b     = (const float*)d_in[8];
    const float* pos_bias = (const float*)d_in[9];
    const float* R_w      = (const float*)d_in[10];
    const float* R_b      = (const float*)d_in[11];
    float* out = (float*)d_out;

    cudaFuncSetAttribute(att_mma,
        cudaFuncAttributeMaxDynamicSharedMemorySize, ATT_SMEM);
    cudaFuncSetAttribute(proj_mma<NT, 0>,
        cudaFuncAttributeMaxDynamicSharedMemorySize, PROJ_SMEM);
    cudaFuncSetAttribute(proj_mma<WINDOW, 1>,
        cudaFuncAttributeMaxDynamicSharedMemorySize, PROJ_SMEM);
    cudaFuncSetAttribute(proj_mma<WINDOW, 2>,
        cudaFuncAttributeMaxDynamicSharedMemorySize, PROJ_SMEM);

    prep_w<<<128, 256>>>(At_w, Ac_w, Bc_w, R_w);

    proj_mma<NT,     0><<<dim3(NB*NT/128,     2), 256, PROJ_SMEM>>>(queries, At_b, 0);
    proj_mma<WINDOW, 1><<<dim3(NB*WINDOW/128, 2), 256, PROJ_SMEM>>>(keys,    Ac_b, 1);
    proj_mma<WINDOW, 2><<<dim3(NB*WINDOW/128, 2), 256, PROJ_SMEM>>>(values,  Bc_b, 2);

    const long long need = (long long)OUT_ELEMS + (long long)ATT_ELEMS;
    const int write_att = ((long long)out_size >= need) ? 1 : 0;
    att_mma<<<NB*NH, 256, ATT_SMEM>>>(pos_bias, out + OUT_ELEMS, write_att);

    out_kernel<<<NB*NT/25, 256>>>(R_b, out);
}